// round 17
// baseline (speedup 1.0000x reference)
#include <cuda_runtime.h>
#include <math.h>

#define NB 15
#define NC 4096
#define BATCH 512
#define ZCH 8               // 8 z-chunks of 64 rows
#define NCC 4               // 4 channel windows of 1024 floats
#define NGROUP (NB * NCC)   // 60 groups of 8 blocks; grid = 480 = single wave

// Scratch (allocation-free): 1.9 MB of partials (written in the last us of
// each block's life -> L2-hot for the group reducer)
__device__ float        g_partial[NGROUP * ZCH * 1024];  // [group][z][1024]
__device__ float2       g_bpart[NGROUP];                 // per group {sum m, sum m^2}
__device__ unsigned int g_gctr[NGROUP];                  // per-group arrival counters
__device__ unsigned int g_ctr;                           // global group counter

// ---------------------------------------------------------------------------
// Single kernel, single wave, R1-k1 addressing (the proven 72%-DRAM pattern):
// block = 64 consecutive rows x 1024-float window; 8 warps sweep a contiguous
// 4 KB. Phase A stores a 4-KB partial. Last arriver of each 8-block group
// reduces 8x4KB (L2-hot) -> float2. Last group computes the loss.
// grid = (NCC, NB, ZCH) = (4, 15, 8) = 480 blocks, block = 256
// ---------------------------------------------------------------------------
__global__ void __launch_bounds__(256) k_loss(const float* __restrict__ in,
                                              float* __restrict__ out)
{
    const int cc  = blockIdx.x;
    const int b   = blockIdx.y;
    const int z   = blockIdx.z;
    const int tid = threadIdx.x;
    const int g   = b * NCC + cc;

    // ---- phase A: EXACT R1-k1 streaming (64 rows x 1024-float window) ----
    const size_t rowstride = (size_t)NB * NC;
    const float* p = in + ((size_t)(z * 64) * NB + b) * NC + cc * 1024 + tid * 4;

    float4 a0 = make_float4(0.f, 0.f, 0.f, 0.f);
    float4 a1 = a0, a2 = a0, a3 = a0;

    #pragma unroll 4
    for (int i = 0; i < 64; i += 4) {
        float4 v0 = *(const float4*)(p + (size_t)(i + 0) * rowstride);
        float4 v1 = *(const float4*)(p + (size_t)(i + 1) * rowstride);
        float4 v2 = *(const float4*)(p + (size_t)(i + 2) * rowstride);
        float4 v3 = *(const float4*)(p + (size_t)(i + 3) * rowstride);
        a0.x += v0.x; a0.y += v0.y; a0.z += v0.z; a0.w += v0.w;
        a1.x += v1.x; a1.y += v1.y; a1.z += v1.z; a1.w += v1.w;
        a2.x += v2.x; a2.y += v2.y; a2.z += v2.z; a2.w += v2.w;
        a3.x += v3.x; a3.y += v3.y; a3.z += v3.z; a3.w += v3.w;
    }

    float4 acc;
    acc.x = (a0.x + a1.x) + (a2.x + a3.x);
    acc.y = (a0.y + a1.y) + (a2.y + a3.y);
    acc.z = (a0.z + a1.z) + (a2.z + a3.z);
    acc.w = (a0.w + a1.w) + (a2.w + a3.w);

    *(float4*)&g_partial[((size_t)g * ZCH + z) * 1024 + tid * 4] = acc;

    // ---- group arrival (release: all threads fence their partial store) ----
    __threadfence();
    __syncthreads();
    __shared__ int sh_grdy;
    if (tid == 0) {
        unsigned int old = atomicAdd(&g_gctr[g], 1u);
        sh_grdy = (old == ZCH - 1) ? 1 : 0;
        if (sh_grdy) g_gctr[g] = 0;   // reset for next replay (sole reader)
    }
    __syncthreads();
    if (!sh_grdy) return;

    // ---- group reduce: 8 x 4 KB L2-hot partials -> (sum m, sum m^2) ----
    __threadfence();   // acquire other blocks' partial writes

    const float4* q = (const float4*)&g_partial[(size_t)g * ZCH * 1024 + tid * 4];

    float4 w0 = q[0 * 256];
    float4 w1 = q[1 * 256];
    float4 w2 = q[2 * 256];
    float4 w3 = q[3 * 256];
    float4 w4 = q[4 * 256];
    float4 w5 = q[5 * 256];
    float4 w6 = q[6 * 256];
    float4 w7 = q[7 * 256];

    float4 t;
    t.x = ((w0.x + w1.x) + (w2.x + w3.x)) + ((w4.x + w5.x) + (w6.x + w7.x));
    t.y = ((w0.y + w1.y) + (w2.y + w3.y)) + ((w4.y + w5.y) + (w6.y + w7.y));
    t.z = ((w0.z + w1.z) + (w2.z + w3.z)) + ((w4.z + w5.z) + (w6.z + w7.z));
    t.w = ((w0.w + w1.w) + (w2.w + w3.w)) + ((w4.w + w5.w) + (w6.w + w7.w));

    const float inv_batch = 1.0f / (float)BATCH;   // exact
    float m0 = t.x * inv_batch;
    float m1 = t.y * inv_batch;
    float m2 = t.z * inv_batch;
    float m3 = t.w * inv_batch;

    float s  = (m0 + m1) + (m2 + m3);
    float s2 = fmaf(m0, m0, m1 * m1) + fmaf(m2, m2, m3 * m3);

    #pragma unroll
    for (int off = 16; off > 0; off >>= 1) {
        s  += __shfl_down_sync(0xffffffffu, s,  off);
        s2 += __shfl_down_sync(0xffffffffu, s2, off);
    }

    __shared__ float rs[8], rs2[8];
    if ((tid & 31) == 0) { rs[tid >> 5] = s; rs2[tid >> 5] = s2; }
    __syncthreads();

    __shared__ int sh_last;
    if (tid == 0) {
        float sum   = ((rs[0] + rs[1]) + (rs[2] + rs[3]))
                    + ((rs[4] + rs[5]) + (rs[6] + rs[7]));
        float sumsq = ((rs2[0] + rs2[1]) + (rs2[2] + rs2[3]))
                    + ((rs2[4] + rs2[5]) + (rs2[6] + rs2[7]));
        g_bpart[g] = make_float2(sum, sumsq);
        __threadfence();
        unsigned int old = atomicAdd(&g_ctr, 1u);
        sh_last = (old == NGROUP - 1) ? 1 : 0;
    }
    __syncthreads();
    if (!sh_last || tid >= 32) return;

    // ---- last group, warp 0: per-base stats + final loss (fp32) ----
    __threadfence();   // acquire all groups' g_bpart

    const int l = tid;
    __shared__ float sh_mean[NB], sh_std[NB];

    if (l < NB) {
        float2 p0 = g_bpart[l * NCC + 0];
        float2 p1 = g_bpart[l * NCC + 1];
        float2 p2 = g_bpart[l * NCC + 2];
        float2 p3 = g_bpart[l * NCC + 3];
        float sum   = (p0.x + p1.x) + (p2.x + p3.x);
        float sumsq = (p0.y + p1.y) + (p2.y + p3.y);
        float mean = sum * (1.0f / (float)NC);            // exact scale
        float var  = (sumsq - sum * sum * (1.0f / (float)NC)) * (1.0f / (float)(NC - 1));
        if (var < 0.f) var = 0.f;
        sh_mean[l] = mean;
        sh_std[l]  = sqrtf(var);
    }
    __syncwarp();

    // groups: [0,3) [3,5) [5,6) [6,10) [10,12) [12,15)
    const int starts[7] = {0, 3, 5, 6, 10, 12, 15};
    const int G = 6;
    const int pi[15] = {0,0,0,0,0, 1,1,1,1, 2,2,2, 3,3, 4};
    const int pj[15] = {1,2,3,4,5, 2,3,4,5, 3,4,5, 4,5, 5};

    __shared__ float sh_ss[6], sh_mn[6], sh_msum[6], sh_pair[15], sh_lt[6];

    if (l < G) {
        const int s0 = starts[l], s1 = starts[l + 1];
        const int ng = s1 - s0;
        if (ng == 1) {
            sh_ss[l]   = sh_std[s0];
            sh_msum[l] = sh_mean[s0];
            sh_mn[l]   = sh_mean[s0];
        } else {
            float ms = 0.f, mm = 0.f;
            for (int k = s0; k < s1; k++) { ms += sh_std[k]; mm += sh_mean[k]; }
            ms /= (float)ng; mm /= (float)ng;
            float vs = 0.f, vm = 0.f;
            for (int k = s0; k < s1; k++) {
                float d = sh_std[k]  - ms; vs = fmaf(d, d, vs);
                float e = sh_mean[k] - mm; vm = fmaf(e, e, vm);
            }
            sh_ss[l]   = sqrtf(vs / (float)(ng - 1));
            sh_msum[l] = sqrtf(vm / (float)(ng - 1));
            sh_mn[l]   = mm;
        }
    }
    __syncwarp();

    if (l < 15) {
        float d1 = sh_ss[pi[l]] - sh_ss[pj[l]];
        float d2 = sh_mn[pi[l]] - sh_mn[pj[l]];
        sh_pair[l] = expf(d1 * d1) + expf(d2 * d2);   // MEAN_STD = 1.0
    }
    __syncwarp();

    if (l < G) {
        float subloss = 5e-5f;
        #pragma unroll
        for (int p2i = 0; p2i < 15; p2i++)
            if (pi[p2i] == l) subloss += sh_pair[p2i];
        sh_lt[l] = logf(1.0f + sh_msum[l] / (subloss + sh_msum[l]));
    }
    __syncwarp();

    if (l == 0) {
        float loss = 0.f;
        #pragma unroll
        for (int g2 = 0; g2 < G; g2++) loss += sh_lt[g2];
        out[0] = loss;
        g_ctr = 0;   // reset for next graph replay
    }
}

// ---------------------------------------------------------------------------
extern "C" void kernel_launch(void* const* d_in, const int* in_sizes, int n_in,
                              void* d_out, int out_size)
{
    const float* meta1 = (const float*)d_in[0];

    dim3 g(NCC, NB, ZCH);   // (4, 15, 8) = 480 blocks = single resident wave
    k_loss<<<g, 256>>>(meta1, (float*)d_out);
}